// round 6
// baseline (speedup 1.0000x reference)
#include <cuda_runtime.h>
#include <cuda_bf16.h>
#include <cstdint>

// Problem constants (match reference)
#define N_B   16
#define T_DIM 4096
#define F_DIM 256
#define PAD_MAX 1228                   // int(0.3 * 4096)
#define TP    (T_DIM + 2 * PAD_MAX)    // 6552

#define OUT_ELEMS (N_B * TP * F_DIM)   // 26,836,992
#define ROW_BYTES (F_DIM * 4)          // 1024

#define SLOTS           16
#define ROWS_PER_BLOCK  64             // 4 chunks of 16
#define BLOCKS_PER_N    ((TP + ROWS_PER_BLOCK - 1) / ROWS_PER_BLOCK)  // 103

__device__ __forceinline__ uint32_t smem_u32(const void* p) {
    uint32_t a;
    asm("{ .reg .u64 t; cvta.to.shared.u64 t, %1; cvt.u32.u64 %0, t; }"
        : "=r"(a) : "l"(p));
    return a;
}

__device__ __forceinline__ void mbar_init(uint32_t mbar, uint32_t count) {
    asm volatile("mbarrier.init.shared.b64 [%0], %1;" :: "r"(mbar), "r"(count) : "memory");
}
__device__ __forceinline__ void mbar_expect_tx(uint32_t mbar, uint32_t bytes) {
    asm volatile("mbarrier.arrive.expect_tx.shared.b64 _, [%0], %1;"
                 :: "r"(mbar), "r"(bytes) : "memory");
}
__device__ __forceinline__ void mbar_wait(uint32_t mbar, uint32_t parity) {
    asm volatile(
        "{\n\t"
        ".reg .pred P;\n\t"
        "WAIT_%=: mbarrier.try_wait.parity.shared.b64 P, [%0], %1, 0x989680;\n\t"
        "@P bra.uni DONE_%=;\n\t"
        "bra.uni WAIT_%=;\n\t"
        "DONE_%=:\n\t"
        "}"
        :: "r"(mbar), "r"(parity) : "memory");
}
__device__ __forceinline__ void bulk_load(uint32_t dst_smem, const void* src, uint32_t mbar) {
    asm volatile(
        "cp.async.bulk.shared::cta.global.mbarrier::complete_tx::bytes [%0], [%1], %2, [%3];"
        :: "r"(dst_smem), "l"(src), "n"(ROW_BYTES), "r"(mbar) : "memory");
}
__device__ __forceinline__ void bulk_store(void* dst, uint32_t src_smem) {
    asm volatile(
        "cp.async.bulk.global.shared::cta.bulk_group [%0], [%1], %2;"
        :: "l"(dst), "r"(src_smem), "n"(ROW_BYTES) : "memory");
}

__global__ __launch_bounds__(32)
void random_shift_tma_kernel(const float* __restrict__ in_,
                             const int*   __restrict__ in_lens,
                             const int*   __restrict__ pad,
                             float* __restrict__ out,
                             int tail_count)
{
    __shared__ __align__(128) float buf[SLOTS][F_DIM];
    __shared__ __align__(128) float zbuf[F_DIM];
    __shared__ __align__(8)   unsigned long long mbar_store[SLOTS];

    if (threadIdx.x != 0) return;   // single driver thread; TMA engine does the work

    const int n = blockIdx.y;
    const int lens = in_lens[n];
    const int p0   = pad[n];
    const int p1   = pad[N_B + n];
    const int out_len = lens + p0 + p1;

    const float* in_n  = in_ + (size_t)n * T_DIM * F_DIM;
    float*       out_n = out + (size_t)n * TP * F_DIM;

    // init zero slot + mbarriers, then fence so the async proxy sees them
    #pragma unroll
    for (int i = 0; i < F_DIM; i++) zbuf[i] = 0.f;
    uint32_t mb[SLOTS];
    #pragma unroll
    for (int i = 0; i < SLOTS; i++) {
        mb[i] = smem_u32(&mbar_store[i]);
        mbar_init(mb[i], 1);
    }
    const uint32_t zslot = smem_u32(zbuf);
    asm volatile("fence.proxy.async.shared::cta;" ::: "memory");

    unsigned parmask = 0;            // bit i = parity to wait for on slot i's next use
    const int t_base = blockIdx.x * ROWS_PER_BLOCK;

    #pragma unroll 1
    for (int c = 0; c < ROWS_PER_BLOCK / SLOTS; c++) {
        const int tc = t_base + c * SLOTS;
        if (tc >= TP) break;

        // Phase A: fire all loads for valid rows in this chunk
        #pragma unroll 1
        for (int i = 0; i < SLOTS; i++) {
            int t = tc + i;
            if (t >= TP) break;
            if (t < out_len) {
                int src;
                if (t < p0)              src = p0 - t;                // left reflect
                else if (t < p0 + lens)  src = t - p0;                 // middle
                else                     src = 2 * lens + p0 - t - 2;  // right reflect
                src = min(max(src, 0), T_DIM - 1);
                mbar_expect_tx(mb[i], ROW_BYTES);
                bulk_load(smem_u32(buf[i]), in_n + (size_t)src * F_DIM, mb[i]);
            }
        }

        // Phase B: as each load lands, fire the store; zero rows store from zbuf
        #pragma unroll 1
        for (int i = 0; i < SLOTS; i++) {
            int t = tc + i;
            if (t >= TP) break;
            float* dst = out_n + (size_t)t * F_DIM;
            if (t < out_len) {
                mbar_wait(mb[i], (parmask >> i) & 1u);
                parmask ^= (1u << i);
                bulk_store(dst, smem_u32(buf[i]));
            } else {
                bulk_store(dst, zslot);
            }
        }

        asm volatile("cp.async.bulk.commit_group;" ::: "memory");
        // drain smem reads before slot reuse next chunk
        asm volatile("cp.async.bulk.wait_group.read 0;" ::: "memory");
    }

    // Fold out_lens tail write into one block (values exact in fp32).
    if (blockIdx.x == 0 && blockIdx.y == 0) {
        for (int ix = 0; ix < tail_count && ix < N_B; ix++) {
            int ol = in_lens[ix] + pad[ix] + pad[N_B + ix];
            out[OUT_ELEMS + ix] = (float)ol;
        }
    }
}

extern "C" void kernel_launch(void* const* d_in, const int* in_sizes, int n_in,
                              void* d_out, int out_size)
{
    const float* in_  = (const float*)d_in[0];
    const int*   lens = (const int*)d_in[1];
    const int*   pad  = (const int*)d_in[2];
    float*       out  = (float*)d_out;

    int tail = out_size - OUT_ELEMS;   // out_lens packed after main tensor (if present)
    if (tail < 0) tail = 0;

    dim3 grid(BLOCKS_PER_N, N_B, 1);   // 103 x 16 = 1648 blocks
    random_shift_tma_kernel<<<grid, 32>>>(in_, lens, pad, out, tail);
}

// round 7
// speedup vs baseline: 1.4719x; 1.4719x over previous
#include <cuda_runtime.h>
#include <cuda_bf16.h>
#include <cstdint>

// Problem constants (match reference)
#define N_B   16
#define T_DIM 4096
#define F_DIM 256
#define PAD_MAX 1228                   // int(0.3 * 4096)
#define TP    (T_DIM + 2 * PAD_MAX)    // 6552

#define OUT_ELEMS (N_B * TP * F_DIM)   // 26,836,992
#define ROW_BYTES (F_DIM * 4)          // 1024

#define ROWS_PER_WARP  4
#define WARPS_PER_BLK  8
#define ROWS_PER_BLK   (ROWS_PER_WARP * WARPS_PER_BLK)           // 32
#define BLOCKS_PER_N   ((TP + ROWS_PER_BLK - 1) / ROWS_PER_BLK)  // 205

__device__ __forceinline__ uint32_t smem_u32(const void* p) {
    uint32_t a;
    asm("{ .reg .u64 t; cvta.to.shared.u64 t, %1; cvt.u32.u64 %0, t; }"
        : "=r"(a) : "l"(p));
    return a;
}
__device__ __forceinline__ void bulk_store_row(void* dst, uint32_t src_smem) {
    asm volatile(
        "cp.async.bulk.global.shared::cta.bulk_group [%0], [%1], %2;"
        :: "l"(dst), "r"(src_smem), "n"(ROW_BYTES) : "memory");
}

__global__ __launch_bounds__(256)
void random_shift_kernel(const float* __restrict__ in_,
                         const int*   __restrict__ in_lens,
                         const int*   __restrict__ pad,
                         float* __restrict__ out,
                         int tail_count)
{
    __shared__ __align__(128) float zbuf[F_DIM];   // 1 KB of zeros for TMA source

    // Cooperative zero of zbuf (256 threads, 256 floats), then make it visible
    // to the async proxy before any bulk store reads it.
    zbuf[threadIdx.x] = 0.f;
    asm volatile("fence.proxy.async.shared::cta;" ::: "memory");
    __syncthreads();

    const int n    = blockIdx.y;
    const int w    = threadIdx.x >> 5;
    const int lane = threadIdx.x & 31;

    // warp-uniform metadata (L1 broadcast hits)
    const int lens = __ldg(&in_lens[n]);
    const int p0   = __ldg(&pad[n]);
    const int p1   = __ldg(&pad[N_B + n]);
    const int out_len = lens + p0 + p1;

    const float* in_n  = in_ + (size_t)n * T_DIM * F_DIM;
    float*       out_n = out + (size_t)n * TP * F_DIM;
    const uint32_t zslot = smem_u32(zbuf);

    const int t0 = blockIdx.x * ROWS_PER_BLK + w * ROWS_PER_WARP;

    // Phase 1: per-row uniform source computation
    const float4* sp[ROWS_PER_WARP];
    bool vld[ROWS_PER_WARP];
    bool inb[ROWS_PER_WARP];
    #pragma unroll
    for (int r = 0; r < ROWS_PER_WARP; r++) {
        int t = t0 + r;
        int src;
        if (t < p0)              src = p0 - t;                // left reflect
        else if (t < p0 + lens)  src = t - p0;                 // middle
        else                     src = 2 * lens + p0 - t - 2;  // right reflect
        src = min(max(src, 0), T_DIM - 1);
        inb[r] = (t < TP);
        vld[r] = (t < out_len);
        sp[r]  = reinterpret_cast<const float4*>(in_n + (size_t)src * F_DIM) + lane;
    }

    // Phase 2: batched loads for valid rows only (MLP up to 8)
    float4 val[ROWS_PER_WARP][2];
    #pragma unroll
    for (int r = 0; r < ROWS_PER_WARP; r++) {
        #pragma unroll
        for (int h = 0; h < 2; h++) {
            val[r][h] = vld[r] ? __ldg(sp[r] + h * 32)
                               : make_float4(0.f, 0.f, 0.f, 0.f);
        }
    }

    // Phase 3: valid rows -> STG.128; zero rows -> one TMA bulk store (lane 0)
    #pragma unroll
    for (int r = 0; r < ROWS_PER_WARP; r++) {
        int t = t0 + r;
        if (!inb[r]) continue;
        float* dst = out_n + (size_t)t * F_DIM;
        if (vld[r]) {
            float4* op = reinterpret_cast<float4*>(dst) + lane;
            #pragma unroll
            for (int h = 0; h < 2; h++) {
                op[h * 32] = val[r][h];
            }
        } else if (lane == 0) {
            bulk_store_row(dst, zslot);   // 1 instr per 1KB row, off the LSU
        }
    }

    // Drain TMA reads of zbuf before the block (and its smem) retires.
    if (lane == 0) {
        asm volatile("cp.async.bulk.commit_group;" ::: "memory");
        asm volatile("cp.async.bulk.wait_group.read 0;" ::: "memory");
    }

    // Fold out_lens tail write into the first block (values exact in fp32).
    if (blockIdx.x == 0 && blockIdx.y == 0 && threadIdx.x < 16) {
        int ix = threadIdx.x;
        if (ix < tail_count) {
            int ol = __ldg(&in_lens[ix]) + __ldg(&pad[ix]) + __ldg(&pad[N_B + ix]);
            out[OUT_ELEMS + ix] = (float)ol;
        }
    }
}

extern "C" void kernel_launch(void* const* d_in, const int* in_sizes, int n_in,
                              void* d_out, int out_size)
{
    const float* in_  = (const float*)d_in[0];
    const int*   lens = (const int*)d_in[1];
    const int*   pad  = (const int*)d_in[2];
    float*       out  = (float*)d_out;

    int tail = out_size - OUT_ELEMS;   // out_lens packed after main tensor (if present)
    if (tail < 0) tail = 0;

    dim3 grid(BLOCKS_PER_N, N_B, 1);   // 205 x 16 = 3280 blocks
    random_shift_kernel<<<grid, 256>>>(in_, lens, pad, out, tail);
}